// round 17
// baseline (speedup 1.0000x reference)
#include <cuda_runtime.h>
#include <math.h>

#define THREADS 256
#define STAGES  12                      // 48 KB ring (static smem cap)
#define DEPTH   11                      // tiles in flight
#define CPT     THREADS                 // chunks (16B) per tile = 1 per thread

__device__ __forceinline__ void cp_async16(void* smem_dst, const void* gsrc) {
    unsigned saddr = (unsigned)__cvta_generic_to_shared(smem_dst);
    asm volatile("cp.async.cg.shared.global [%0], [%1], 16;\n"
                 :: "r"(saddr), "l"(gsrc));
}
__device__ __forceinline__ void cp_async_commit() {
    asm volatile("cp.async.commit_group;\n" ::: "memory");
}
template<int N>
__device__ __forceinline__ void cp_async_wait() {
    asm volatile("cp.async.wait_group %0;\n" :: "n"(N) : "memory");
}

__global__ __launch_bounds__(THREADS)
void wrpl_row_kernel(const float* __restrict__ scores,
                     const int* __restrict__ targets,
                     float* __restrict__ out,
                     int B, int C)
{
    // Each thread owns one 16B slot per stage -> no cross-thread smem sharing,
    // no __syncthreads in the streaming loop. wait_group orders own write/read.
    __shared__ float4 buf[STAGES][CPT];          // 48 KB

    const int row = blockIdx.x;
    const float* s = scores + (size_t)row * (size_t)C;
    const int t = targets[row];

    const float gt  = __ldg(s + t);
    const float thr = gt - 1.0f;        // l > 0  <=>  s > gt - 1

    const unsigned nChunks = (unsigned)(C >> 2); // float4 chunks per row (C % 4 == 0)
    const unsigned nTiles  = (nChunks + CPT - 1u) / CPT;
    const int      tb      = t >> 2;    // chunk containing the target

    const float4* s4 = reinterpret_cast<const float4*>(s);
    const unsigned td = threadIdx.x;

    int   cnt_rank = 0;   // #{j<t: s_j >= gt} + #{j>t: s_j > gt} = rank-1
    int   cnt_pos  = 0;   // #{j != t : s_j > thr}
    float xsum     = 0.0f;

    // ---- prologue: fill DEPTH stages ----
    #pragma unroll
    for (int pt = 0; pt < DEPTH; ++pt) {
        unsigned c4 = (unsigned)pt * CPT + td;
        if ((unsigned)pt < nTiles && c4 < nChunks)
            cp_async16(&buf[pt][td], s4 + c4);
        cp_async_commit();
    }

#define PROC_GE(xv) { float x = (xv); cnt_rank += (x >= gt); bool p = (x > thr); cnt_pos += p; if (p) xsum += x; }
#define PROC_GT(xv) { float x = (xv); cnt_rank += (x >  gt); bool p = (x > thr); cnt_pos += p; if (p) xsum += x; }

    // ---- streaming loop: 1 issue + 1 wait per tile, no barriers ----
    // ring stages tracked with wrap counters (one SEL each; no modulo chain)
    int rd_st = 0;                       // stage of tile being consumed
    int wr_st = DEPTH % STAGES;          // stage of tile being issued (tile+DEPTH)
    for (unsigned tile = 0; tile < nTiles; ++tile) {
        const unsigned it = tile + DEPTH;
        if (it < nTiles) {
            unsigned c4i = it * CPT + td;
            if (c4i < nChunks)
                cp_async16(&buf[wr_st][td], s4 + c4i);
        }
        cp_async_commit();
        cp_async_wait<DEPTH>();          // own tile `tile` is complete

        const int c4 = (int)(tile * CPT + td);
        if (c4 < (int)nChunks) {
            float4 v = buf[rd_st][td];
            if (c4 < tb) {               // all idx < t
                PROC_GE(v.x) PROC_GE(v.y) PROC_GE(v.z) PROC_GE(v.w)
            } else if (c4 > tb) {        // all idx > t
                PROC_GT(v.x) PROC_GT(v.y) PROC_GT(v.z) PROC_GT(v.w)
            } else {                     // boundary chunk: contains j == t
                const float xv[4] = {v.x, v.y, v.z, v.w};
                const int base = c4 << 2;
                #pragma unroll
                for (int e = 0; e < 4; ++e) {
                    int idx = base + e;
                    if (idx == t) continue;
                    float x = xv[e];
                    cnt_rank += (idx < t) ? (x >= gt) : (x > gt);
                    bool p = (x > thr);
                    cnt_pos += p;
                    if (p) xsum += x;
                }
            }
        }
        rd_st = (rd_st + 1 == STAGES) ? 0 : rd_st + 1;
        wr_st = (wr_st + 1 == STAGES) ? 0 : wr_st + 1;
    }
#undef PROC_GE
#undef PROC_GT

    // ---- block reduction ----
    const unsigned FULL = 0xFFFFFFFFu;
    #pragma unroll
    for (int off = 16; off > 0; off >>= 1) {
        cnt_rank += __shfl_down_sync(FULL, cnt_rank, off);
        cnt_pos  += __shfl_down_sync(FULL, cnt_pos,  off);
        xsum     += __shfl_down_sync(FULL, xsum,     off);
    }

    __shared__ int   sh_rk [THREADS / 32];
    __shared__ int   sh_pos[THREADS / 32];
    __shared__ float sh_xs [THREADS / 32];

    const unsigned lane = td & 31u;
    const unsigned wid  = td >> 5;
    if (lane == 0) {
        sh_rk[wid]  = cnt_rank;
        sh_pos[wid] = cnt_pos;
        sh_xs[wid]  = xsum;
    }
    __syncthreads();

    if (td == 0) {
        int   rk = 0, p = 0;
        float xs = 0.0f;
        #pragma unroll
        for (int i = 0; i < THREADS / 32; i++) {
            rk += sh_rk[i]; p += sh_pos[i]; xs += sh_xs[i];
        }

        const int rank = rk + 1;
        const float hinge = xs - (float)p * thr;

        // harmonic number H(rank)
        double H;
        if (rank <= 64) {
            H = 0.0;
            for (int i = 1; i <= rank; i++) H += 1.0 / (double)i;
        } else {
            double n  = (double)rank;
            double n2 = n * n;
            H = log(n) + 0.57721566490153286
              + 1.0 / (2.0 * n) - 1.0 / (12.0 * n2) + 1.0 / (120.0 * n2 * n2);
        }

        float npos = (float)p + 1e-7f;
        float loss = (float)H / npos * hinge;
        atomicAdd(out, loss / (float)B);
    }
}

extern "C" void kernel_launch(void* const* d_in, const int* in_sizes, int n_in,
                              void* d_out, int out_size)
{
    const float* scores  = (const float*)d_in[0];
    const int*   targets = (const int*)d_in[1];
    float*       out     = (float*)d_out;

    const int B = in_sizes[1];
    const int C = in_sizes[0] / B;

    // graph memset node: cheaper than a zeroing kernel launch
    cudaMemsetAsync(out, 0, sizeof(float));
    wrpl_row_kernel<<<B, THREADS>>>(scores, targets, out, B, C);
}